// round 1
// baseline (speedup 1.0000x reference)
#include <cuda_runtime.h>

#define CC   112
#define CLSN 20
#define NSMAX 8192
#define NQMAX 20000

// ---------------- scratch (device globals; no allocation) ----------------
__device__ float  g_logits[NSMAX];
__device__ float  g_a[NSMAX];
__device__ float  g_part[32 * CC];
__device__ float  g_gate[CC];
__device__ float  g_W1g[CC * CC];
__device__ float  g_Wf[CC * CLSN];
__device__ float4 g_s4[NSMAX];
__device__ float  g_FS1[NSMAX * CC];
__device__ float  g_XW[NQMAX * CC];

// ---------------- K0: static prep: s4 = (sx,sy,sz,|s|^2), Wf = W2@Wcls ----
__global__ void k_prep(const float* __restrict__ coords_s,
                       const float* __restrict__ W2,
                       const float* __restrict__ Wcls, int NS)
{
    int idx = blockIdx.x * blockDim.x + threadIdx.x;
    if (idx < NS) {
        float x = coords_s[idx * 3 + 0];
        float y = coords_s[idx * 3 + 1];
        float z = coords_s[idx * 3 + 2];
        g_s4[idx] = make_float4(x, y, z, x * x + y * y + z * z);
    } else {
        int j = idx - NS;
        if (j < CC * CLSN) {
            int c = j / CLSN, o = j % CLSN;
            float s = 0.f;
            #pragma unroll 8
            for (int k = 0; k < CC; k++)
                s = fmaf(W2[c * CC + k], Wcls[k * CLSN + o], s);
            g_Wf[j] = s;
        }
    }
}

// ---------------- K1: logits[i] = feat_s7[i,:] . w_attn --------------------
__global__ void k_logits(const float* __restrict__ F,
                         const float* __restrict__ w, int NS)
{
    int gt   = blockIdx.x * blockDim.x + threadIdx.x;
    int warp = gt >> 5;
    int lane = gt & 31;
    int nwarps = (gridDim.x * blockDim.x) >> 5;
    float w0 = w[lane], w1 = w[lane + 32], w2 = w[lane + 64];
    float w3 = (lane < 16) ? w[lane + 96] : 0.f;
    for (int i = warp; i < NS; i += nwarps) {
        const float* row = F + i * CC;
        float s = row[lane] * w0 + row[lane + 32] * w1 + row[lane + 64] * w2;
        if (lane < 16) s += row[lane + 96] * w3;
        #pragma unroll
        for (int o = 16; o; o >>= 1) s += __shfl_xor_sync(0xffffffffu, s, o);
        if (lane == 0) g_logits[i] = s;
    }
}

// ---------------- K2: softmax over logits -> g_a --------------------------
__global__ void k_softmax(int NS)
{
    __shared__ float red[1024];
    int t = threadIdx.x;
    float mx = -1e30f;
    for (int i = t; i < NS; i += 1024) mx = fmaxf(mx, g_logits[i]);
    red[t] = mx; __syncthreads();
    for (int s = 512; s; s >>= 1) { if (t < s) red[t] = fmaxf(red[t], red[t + s]); __syncthreads(); }
    mx = red[0]; __syncthreads();
    float sum = 0.f;
    for (int i = t; i < NS; i += 1024) sum += __expf(g_logits[i] - mx);
    red[t] = sum; __syncthreads();
    for (int s = 512; s; s >>= 1) { if (t < s) red[t] += red[t + s]; __syncthreads(); }
    float inv = 1.f / red[0];
    for (int i = t; i < NS; i += 1024) g_a[i] = __expf(g_logits[i] - mx) * inv;
}

// ---------------- K3: partial weighted sums g_part[b][c] = sum a_i f[i][c] -
__global__ void k_gpool(const float* __restrict__ F, int NS)
{
    __shared__ float sacc[8][CC];
    int w = threadIdx.x >> 5, lane = threadIdx.x & 31;
    float p0 = 0.f, p1 = 0.f, p2 = 0.f, p3 = 0.f;
    int base = blockIdx.x * 256 + w * 32;
    for (int t = 0; t < 32; t++) {
        int i = base + t;
        if (i < NS) {
            float ai = g_a[i];
            const float* row = F + i * CC;
            p0 += ai * row[lane];
            p1 += ai * row[lane + 32];
            p2 += ai * row[lane + 64];
            if (lane < 16) p3 += ai * row[lane + 96];
        }
    }
    sacc[w][lane]      = p0;
    sacc[w][lane + 32] = p1;
    sacc[w][lane + 64] = p2;
    if (lane < 16) sacc[w][lane + 96] = p3;
    __syncthreads();
    if (threadIdx.x < CC) {
        float s = 0.f;
        #pragma unroll
        for (int k = 0; k < 8; k++) s += sacc[k][threadIdx.x];
        g_part[blockIdx.x * CC + threadIdx.x] = s;
    }
}

// ---------------- K4: gate[c] = sigmoid(sum_b part[b][c]) ------------------
__global__ void k_gate(int nparts)
{
    int c = threadIdx.x;
    if (c < CC) {
        float s = 0.f;
        for (int b = 0; b < nparts; b++) s += g_part[b * CC + c];
        g_gate[c] = 1.f / (1.f + __expf(-s));
    }
}

// ---------------- K5: W1g[r][c] = gate[r]*W1[r][c]*gamma[c] ----------------
__global__ void k_w1g(const float* __restrict__ W1, const float* __restrict__ gamma)
{
    int idx = blockIdx.x * blockDim.x + threadIdx.x;
    if (idx < CC * CC) {
        int r = idx / CC, c = idx - r * CC;
        g_W1g[idx] = g_gate[r] * W1[idx] * gamma[c];
    }
}

// ---------------- K6/K7: tiled SGEMM, N=K=112 ------------------------------
// mode 0: out = g_FS1 = A @ Bext, col-scaled by colscale (gamma)
// mode 1: out = g_XW  = A @ g_W1g
__global__ void k_sgemm112(const float* __restrict__ A,
                           const float* __restrict__ Bext,
                           int M, int mode,
                           const float* __restrict__ colscale)
{
    __shared__ float As[64][57];
    __shared__ float Bs[56][112];
    const float* B = mode ? g_W1g : Bext;
    float*      Cm = mode ? g_XW  : g_FS1;
    int tx = threadIdx.x;
    int m0 = blockIdx.x * 64;
    float acc[4][7];
    #pragma unroll
    for (int i = 0; i < 4; i++)
        #pragma unroll
        for (int j = 0; j < 7; j++) acc[i][j] = 0.f;
    int rg = (tx >> 4) << 2;     // 0..60 step 4
    int cg = (tx & 15) * 7;      // 0..105 step 7
    for (int k0 = 0; k0 < CC; k0 += 56) {
        for (int idx = tx; idx < 64 * 56; idx += 256) {
            int r = idx / 56, k = idx - r * 56;
            int gr = m0 + r;
            As[r][k] = (gr < M) ? A[gr * CC + k0 + k] : 0.f;
        }
        for (int idx = tx; idx < 56 * 112; idx += 256) {
            int k = idx / 112, c = idx - k * 112;
            Bs[k][c] = B[(k0 + k) * CC + c];
        }
        __syncthreads();
        #pragma unroll 4
        for (int k = 0; k < 56; k++) {
            float a0 = As[rg][k], a1 = As[rg + 1][k], a2 = As[rg + 2][k], a3 = As[rg + 3][k];
            float b[7];
            #pragma unroll
            for (int j = 0; j < 7; j++) b[j] = Bs[k][cg + j];
            #pragma unroll
            for (int j = 0; j < 7; j++) {
                acc[0][j] = fmaf(a0, b[j], acc[0][j]);
                acc[1][j] = fmaf(a1, b[j], acc[1][j]);
                acc[2][j] = fmaf(a2, b[j], acc[2][j]);
                acc[3][j] = fmaf(a3, b[j], acc[3][j]);
            }
        }
        __syncthreads();
    }
    #pragma unroll
    for (int i = 0; i < 4; i++) {
        int gr = m0 + rg + i;
        if (gr < M) {
            #pragma unroll
            for (int j = 0; j < 7; j++) {
                float v = acc[i][j];
                if (colscale) v *= colscale[cg + j];
                Cm[gr * CC + cg + j] = v;
            }
        }
    }
}

// ---------------- K8: fused kNN + gather + BN/ReLU + classifier ------------
__global__ void k_final(const float* __restrict__ coords_q,
                        const float* __restrict__ beta,
                        const float* __restrict__ bcls,
                        float* __restrict__ out,
                        int NQ, int NS)
{
    __shared__ float Wf[CC * CLSN];
    __shared__ float sbeta[CC];
    __shared__ float sb[CLSN];
    int tx = threadIdx.x;
    for (int i = tx; i < CC * CLSN; i += 128) Wf[i] = g_Wf[i];
    if (tx < CC)  sbeta[tx] = beta[tx];
    if (tx < CLSN) sb[tx] = bcls[tx];
    __syncthreads();

    int q = blockIdx.x * 128 + tx;
    if (q >= NQ) return;

    float qx = coords_q[q * 3 + 0];
    float qy = coords_q[q * 3 + 1];
    float qz = coords_q[q * 3 + 2];
    float nx = -2.f * qx, ny = -2.f * qy, nz = -2.f * qz;

    // top-3 smallest of v = |s|^2 - 2 q.s  (== d2 shifted by |q|^2)
    float b0 = 1e30f, b1 = 1e30f, b2 = 1e30f;
    int   i0 = 0, i1 = 0, i2 = 0;

    int j = 0;
    for (; j + 3 < NS; j += 4) {
        float4 s0 = __ldg(&g_s4[j + 0]);
        float4 s1 = __ldg(&g_s4[j + 1]);
        float4 s2 = __ldg(&g_s4[j + 2]);
        float4 s3 = __ldg(&g_s4[j + 3]);
        float v0 = fmaf(s0.x, nx, fmaf(s0.y, ny, fmaf(s0.z, nz, s0.w)));
        float v1 = fmaf(s1.x, nx, fmaf(s1.y, ny, fmaf(s1.z, nz, s1.w)));
        float v2 = fmaf(s2.x, nx, fmaf(s2.y, ny, fmaf(s2.z, nz, s2.w)));
        float v3 = fmaf(s3.x, nx, fmaf(s3.y, ny, fmaf(s3.z, nz, s3.w)));
        #pragma unroll
        for (int u = 0; u < 4; u++) {
            float v = (u == 0) ? v0 : (u == 1) ? v1 : (u == 2) ? v2 : v3;
            int   jj = j + u;
            if (v < b2) {
                if (v < b1) {
                    b2 = b1; i2 = i1;
                    if (v < b0) { b1 = b0; i1 = i0; b0 = v; i0 = jj; }
                    else        { b1 = v;  i1 = jj; }
                } else { b2 = v; i2 = jj; }
            }
        }
    }
    for (; j < NS; j++) {
        float4 s = __ldg(&g_s4[j]);
        float v = fmaf(s.x, nx, fmaf(s.y, ny, fmaf(s.z, nz, s.w)));
        if (v < b2) {
            if (v < b1) {
                b2 = b1; i2 = i1;
                if (v < b0) { b1 = b0; i1 = i0; b0 = v; i0 = j; }
                else        { b1 = v;  i1 = j; }
            } else { b2 = v; i2 = j; }
        }
    }

    // softmax(-d2) over the 3 (shift-invariant)
    float e1 = __expf(b0 - b1);
    float e2 = __expf(b0 - b2);
    float inv = 1.f / (1.f + e1 + e2);
    float w0 = inv, w1 = e1 * inv, w2 = e2 * inv;

    const float4* xw = (const float4*)(g_XW + (size_t)q * CC);
    const float4* f0 = (const float4*)(g_FS1 + (size_t)i0 * CC);
    const float4* f1 = (const float4*)(g_FS1 + (size_t)i1 * CC);
    const float4* f2 = (const float4*)(g_FS1 + (size_t)i2 * CC);

    float acc[CLSN];
    #pragma unroll
    for (int o = 0; o < CLSN; o++) acc[o] = sb[o];

    for (int c4 = 0; c4 < CC / 4; c4++) {
        float4 x  = xw[c4];
        float4 a0 = f0[c4];
        float4 a1 = f1[c4];
        float4 a2 = f2[c4];
        int cb = c4 * 4;
        float h[4];
        h[0] = x.x + w0 * a0.x + w1 * a1.x + w2 * a2.x + sbeta[cb + 0];
        h[1] = x.y + w0 * a0.y + w1 * a1.y + w2 * a2.y + sbeta[cb + 1];
        h[2] = x.z + w0 * a0.z + w1 * a1.z + w2 * a2.z + sbeta[cb + 2];
        h[3] = x.w + w0 * a0.w + w1 * a1.w + w2 * a2.w + sbeta[cb + 3];
        #pragma unroll
        for (int u = 0; u < 4; u++) {
            float hv = fmaxf(h[u], 0.f);
            const float* wrow = &Wf[(cb + u) * CLSN];
            #pragma unroll
            for (int o = 0; o < CLSN; o++) acc[o] = fmaf(hv, wrow[o], acc[o]);
        }
    }

    float* op = out + (size_t)q * CLSN;
    #pragma unroll
    for (int o = 0; o < CLSN; o++) op[o] = acc[o];
}

// ---------------- launch ---------------------------------------------------
extern "C" void kernel_launch(void* const* d_in, const int* in_sizes, int n_in,
                              void* d_out, int out_size)
{
    const float* coords_q = (const float*)d_in[0];
    const float* coords_s = (const float*)d_in[1];
    const float* x7       = (const float*)d_in[2];
    const float* feat_s7  = (const float*)d_in[3];
    const float* feat_s   = (const float*)d_in[4];
    const float* w_attn   = (const float*)d_in[5];
    const float* W1       = (const float*)d_in[6];
    const float* gamma    = (const float*)d_in[7];
    const float* beta     = (const float*)d_in[8];
    const float* W2       = (const float*)d_in[9];
    const float* W_cls    = (const float*)d_in[10];
    const float* b_cls    = (const float*)d_in[11];
    float* out = (float*)d_out;

    int NQ = in_sizes[0] / 3;
    int NS = in_sizes[1] / 3;
    int nparts = (NS + 255) / 256;

    k_prep<<<(NS + CC * CLSN + 255) / 256, 256>>>(coords_s, W2, W_cls, NS);
    k_logits<<<32, 256>>>(feat_s7, w_attn, NS);
    k_softmax<<<1, 1024>>>(NS);
    k_gpool<<<nparts, 256>>>(feat_s7, NS);
    k_gate<<<1, 128>>>(nparts);
    k_w1g<<<(CC * CC + 255) / 256, 256>>>(W1, gamma);
    // FS1 = feat_s @ W1_bot, col-scaled by gamma
    k_sgemm112<<<(NS + 63) / 64, 256>>>(feat_s, W1 + CC * CC, NS, 0, gamma);
    // XW = x7 @ W1g (gate+gamma folded)
    k_sgemm112<<<(NQ + 63) / 64, 256>>>(x7, nullptr, NQ, 1, nullptr);
    k_final<<<(NQ + 127) / 128, 128>>>(coords_q, beta, b_cls, out, NQ, NS);
}

// round 2
// speedup vs baseline: 1.8045x; 1.8045x over previous
#include <cuda_runtime.h>

#define CC    112
#define CLSN  20
#define NSMAX 8192
#define NQMAX 20000
#define PARTS 8

// ---------------- scratch (device globals; no allocation) ----------------
__device__ float  g_logits[NSMAX];
__device__ float  g_a[NSMAX];
__device__ float  g_part[128 * CC];
__device__ float  g_gate[CC];
__device__ float  g_Wf[CC * CLSN];
__device__ float4 g_s4[NSMAX];
__device__ float  g_FS1[NSMAX * CC];
__device__ float  g_XW[NQMAX * CC];

// ---------------- K0: s4 = (sx,sy,sz,|s|^2), Wf = W2@Wcls ------------------
__global__ void k_prep(const float* __restrict__ coords_s,
                       const float* __restrict__ W2,
                       const float* __restrict__ Wcls, int NS)
{
    int idx = blockIdx.x * blockDim.x + threadIdx.x;
    if (idx < NS) {
        float x = coords_s[idx * 3 + 0];
        float y = coords_s[idx * 3 + 1];
        float z = coords_s[idx * 3 + 2];
        g_s4[idx] = make_float4(x, y, z, x * x + y * y + z * z);
    } else {
        int j = idx - NS;
        if (j < CC * CLSN) {
            int c = j / CLSN, o = j % CLSN;
            float s = 0.f;
            #pragma unroll 8
            for (int k = 0; k < CC; k++)
                s = fmaf(W2[c * CC + k], Wcls[k * CLSN + o], s);
            g_Wf[j] = s;
        }
    }
}

// ---------------- K1: logits[i] = feat_s7[i,:] . w_attn --------------------
__global__ void k_logits(const float* __restrict__ F,
                         const float* __restrict__ w, int NS)
{
    int gt   = blockIdx.x * blockDim.x + threadIdx.x;
    int warp = gt >> 5;
    int lane = gt & 31;
    int nwarps = (gridDim.x * blockDim.x) >> 5;
    float w0 = w[lane], w1 = w[lane + 32], w2 = w[lane + 64];
    float w3 = (lane < 16) ? w[lane + 96] : 0.f;
    for (int i = warp; i < NS; i += nwarps) {
        const float* row = F + i * CC;
        float s = row[lane] * w0 + row[lane + 32] * w1 + row[lane + 64] * w2;
        if (lane < 16) s += row[lane + 96] * w3;
        #pragma unroll
        for (int o = 16; o; o >>= 1) s += __shfl_xor_sync(0xffffffffu, s, o);
        if (lane == 0) g_logits[i] = s;
    }
}

// ---------------- K2: softmax over logits -> g_a --------------------------
__global__ void k_softmax(int NS)
{
    __shared__ float red[1024];
    int t = threadIdx.x;
    float mx = -1e30f;
    for (int i = t; i < NS; i += 1024) mx = fmaxf(mx, g_logits[i]);
    red[t] = mx; __syncthreads();
    for (int s = 512; s; s >>= 1) { if (t < s) red[t] = fmaxf(red[t], red[t + s]); __syncthreads(); }
    mx = red[0]; __syncthreads();
    float sum = 0.f;
    for (int i = t; i < NS; i += 1024) sum += __expf(g_logits[i] - mx);
    red[t] = sum; __syncthreads();
    for (int s = 512; s; s >>= 1) { if (t < s) red[t] += red[t + s]; __syncthreads(); }
    float inv = 1.f / red[0];
    for (int i = t; i < NS; i += 1024) g_a[i] = __expf(g_logits[i] - mx) * inv;
}

// ---------------- K3: partial weighted sums g_part[b][c] -------------------
__global__ void k_gpool(const float* __restrict__ F, int NS)
{
    __shared__ float sacc[8][CC];
    int w = threadIdx.x >> 5, lane = threadIdx.x & 31;
    float p0 = 0.f, p1 = 0.f, p2 = 0.f, p3 = 0.f;
    int base = blockIdx.x * 64 + w * 8;        // 8 rows per warp
    #pragma unroll
    for (int t = 0; t < 8; t++) {
        int i = base + t;
        if (i < NS) {
            float ai = g_a[i];
            const float* row = F + i * CC;
            p0 = fmaf(ai, row[lane], p0);
            p1 = fmaf(ai, row[lane + 32], p1);
            p2 = fmaf(ai, row[lane + 64], p2);
            if (lane < 16) p3 = fmaf(ai, row[lane + 96], p3);
        }
    }
    sacc[w][lane]      = p0;
    sacc[w][lane + 32] = p1;
    sacc[w][lane + 64] = p2;
    if (lane < 16) sacc[w][lane + 96] = p3;
    __syncthreads();
    if (threadIdx.x < CC) {
        float s = 0.f;
        #pragma unroll
        for (int k = 0; k < 8; k++) s += sacc[k][threadIdx.x];
        g_part[blockIdx.x * CC + threadIdx.x] = s;
    }
}

// ---------------- K4: gate[c] = sigmoid(sum_b part[b][c]) ------------------
__global__ void k_gate(int nparts)
{
    int c = threadIdx.x;
    if (c < CC) {
        float s = 0.f;
        for (int b = 0; b < nparts; b++) s += g_part[b * CC + c];
        g_gate[c] = 1.f / (1.f + __expf(-s));
    }
}

// ---------------- K5/K6: tiled SGEMM, N=K=112 ------------------------------
// C[M,112] = (rowscale? diag(rs):I) applied to B rows during staging,
// colscale (gamma) applied at epilogue.
__global__ void k_sgemm112(const float* __restrict__ A,
                           const float* __restrict__ B,
                           float* __restrict__ Cm,
                           int M, int use_gate,
                           const float* __restrict__ colscale)
{
    __shared__ float As[64][57];
    __shared__ float Bs[56][112];
    int tx = threadIdx.x;
    int m0 = blockIdx.x * 64;
    float acc[4][7];
    #pragma unroll
    for (int i = 0; i < 4; i++)
        #pragma unroll
        for (int j = 0; j < 7; j++) acc[i][j] = 0.f;
    int rg = (tx >> 4) << 2;     // 0..60 step 4
    int cg = (tx & 15) * 7;      // 0..105 step 7
    for (int k0 = 0; k0 < CC; k0 += 56) {
        for (int idx = tx; idx < 64 * 56; idx += 256) {
            int r = idx / 56, k = idx - r * 56;
            int gr = m0 + r;
            As[r][k] = (gr < M) ? A[gr * CC + k0 + k] : 0.f;
        }
        for (int idx = tx; idx < 56 * 112; idx += 256) {
            int k = idx / 112, c = idx - k * 112;
            float v = B[(k0 + k) * CC + c];
            if (use_gate) v *= g_gate[k0 + k];
            Bs[k][c] = v;
        }
        __syncthreads();
        #pragma unroll 4
        for (int k = 0; k < 56; k++) {
            float a0 = As[rg][k], a1 = As[rg + 1][k], a2 = As[rg + 2][k], a3 = As[rg + 3][k];
            float b[7];
            #pragma unroll
            for (int j = 0; j < 7; j++) b[j] = Bs[k][cg + j];
            #pragma unroll
            for (int j = 0; j < 7; j++) {
                acc[0][j] = fmaf(a0, b[j], acc[0][j]);
                acc[1][j] = fmaf(a1, b[j], acc[1][j]);
                acc[2][j] = fmaf(a2, b[j], acc[2][j]);
                acc[3][j] = fmaf(a3, b[j], acc[3][j]);
            }
        }
        __syncthreads();
    }
    float cs[7];
    #pragma unroll
    for (int j = 0; j < 7; j++) cs[j] = colscale[cg + j];
    #pragma unroll
    for (int i = 0; i < 4; i++) {
        int gr = m0 + rg + i;
        if (gr < M) {
            #pragma unroll
            for (int j = 0; j < 7; j++)
                Cm[gr * CC + cg + j] = acc[i][j] * cs[j];
        }
    }
}

// ---------------- K7: fused kNN (split-scan) + gather + ReLU + classifier --
__global__ void k_final(const float* __restrict__ coords_q,
                        const float* __restrict__ beta,
                        const float* __restrict__ bcls,
                        float* __restrict__ out,
                        int NQ, int NS)
{
    __shared__ float Wf[CC * CLSN];
    __shared__ float sbeta[CC];
    __shared__ float sb[CLSN];
    __shared__ float cv[PARTS][32][3];
    __shared__ int   ci[PARTS][32][3];
    int tx = threadIdx.x;
    int qlocal = tx & 31, part = tx >> 5;

    for (int i = tx; i < CC * CLSN; i += 256) Wf[i] = g_Wf[i];
    if (tx < CC)   sbeta[tx] = beta[tx];
    if (tx < CLSN) sb[tx] = bcls[tx];
    __syncthreads();

    int q = blockIdx.x * 32 + qlocal;
    bool valid = (q < NQ);
    float nx = 0.f, ny = 0.f, nz = 0.f;
    if (valid) {
        nx = -2.f * coords_q[q * 3 + 0];
        ny = -2.f * coords_q[q * 3 + 1];
        nz = -2.f * coords_q[q * 3 + 2];
    }

    int per = NS / PARTS;
    int jb = part * per;
    int je = (part == PARTS - 1) ? NS : jb + per;

    // top-3 smallest of v = |s|^2 - 2 q.s  (shift of d2 by |q|^2)
    float b0 = 1e30f, b1 = 1e30f, b2 = 1e30f;
    int   i0 = 0, i1 = 0, i2 = 0;

    int j = jb;
    for (; j + 3 < je; j += 4) {
        float4 s0 = __ldg(&g_s4[j + 0]);
        float4 s1 = __ldg(&g_s4[j + 1]);
        float4 s2 = __ldg(&g_s4[j + 2]);
        float4 s3 = __ldg(&g_s4[j + 3]);
        float v0 = fmaf(s0.x, nx, fmaf(s0.y, ny, fmaf(s0.z, nz, s0.w)));
        float v1 = fmaf(s1.x, nx, fmaf(s1.y, ny, fmaf(s1.z, nz, s1.w)));
        float v2 = fmaf(s2.x, nx, fmaf(s2.y, ny, fmaf(s2.z, nz, s2.w)));
        float v3 = fmaf(s3.x, nx, fmaf(s3.y, ny, fmaf(s3.z, nz, s3.w)));
        #pragma unroll
        for (int u = 0; u < 4; u++) {
            float v = (u == 0) ? v0 : (u == 1) ? v1 : (u == 2) ? v2 : v3;
            int   jj = j + u;
            if (v < b2) {
                if (v < b1) {
                    b2 = b1; i2 = i1;
                    if (v < b0) { b1 = b0; i1 = i0; b0 = v; i0 = jj; }
                    else        { b1 = v;  i1 = jj; }
                } else { b2 = v; i2 = jj; }
            }
        }
    }
    for (; j < je; j++) {
        float4 s = __ldg(&g_s4[j]);
        float v = fmaf(s.x, nx, fmaf(s.y, ny, fmaf(s.z, nz, s.w)));
        if (v < b2) {
            if (v < b1) {
                b2 = b1; i2 = i1;
                if (v < b0) { b1 = b0; i1 = i0; b0 = v; i0 = j; }
                else        { b1 = v;  i1 = j; }
            } else { b2 = v; i2 = j; }
        }
    }

    cv[part][qlocal][0] = b0; ci[part][qlocal][0] = i0;
    cv[part][qlocal][1] = b1; ci[part][qlocal][1] = i1;
    cv[part][qlocal][2] = b2; ci[part][qlocal][2] = i2;
    __syncthreads();

    if (part != 0 || !valid) return;

    // merge (ascending partition order + strict < keeps lowest index on ties)
    b0 = cv[0][qlocal][0]; i0 = ci[0][qlocal][0];
    b1 = cv[0][qlocal][1]; i1 = ci[0][qlocal][1];
    b2 = cv[0][qlocal][2]; i2 = ci[0][qlocal][2];
    #pragma unroll
    for (int p = 1; p < PARTS; p++) {
        #pragma unroll
        for (int k = 0; k < 3; k++) {
            float v = cv[p][qlocal][k];
            int  jj = ci[p][qlocal][k];
            if (v < b2) {
                if (v < b1) {
                    b2 = b1; i2 = i1;
                    if (v < b0) { b1 = b0; i1 = i0; b0 = v; i0 = jj; }
                    else        { b1 = v;  i1 = jj; }
                } else { b2 = v; i2 = jj; }
            }
        }
    }

    // softmax(-d2) over the 3 (shift-invariant)
    float e1 = __expf(b0 - b1);
    float e2 = __expf(b0 - b2);
    float inv = 1.f / (1.f + e1 + e2);
    float w0 = inv, w1 = e1 * inv, w2 = e2 * inv;

    const float4* xw = (const float4*)(g_XW + (size_t)q * CC);
    const float4* f0 = (const float4*)(g_FS1 + (size_t)i0 * CC);
    const float4* f1 = (const float4*)(g_FS1 + (size_t)i1 * CC);
    const float4* f2 = (const float4*)(g_FS1 + (size_t)i2 * CC);

    float acc[CLSN];
    #pragma unroll
    for (int o = 0; o < CLSN; o++) acc[o] = sb[o];

    for (int c4 = 0; c4 < CC / 4; c4++) {
        float4 x  = xw[c4];
        float4 a0 = f0[c4];
        float4 a1 = f1[c4];
        float4 a2 = f2[c4];
        int cb = c4 * 4;
        float h[4];
        h[0] = x.x + w0 * a0.x + w1 * a1.x + w2 * a2.x + sbeta[cb + 0];
        h[1] = x.y + w0 * a0.y + w1 * a1.y + w2 * a2.y + sbeta[cb + 1];
        h[2] = x.z + w0 * a0.z + w1 * a1.z + w2 * a2.z + sbeta[cb + 2];
        h[3] = x.w + w0 * a0.w + w1 * a1.w + w2 * a2.w + sbeta[cb + 3];
        #pragma unroll
        for (int u = 0; u < 4; u++) {
            float hv = fmaxf(h[u], 0.f);
            const float* wrow = &Wf[(cb + u) * CLSN];
            #pragma unroll
            for (int o = 0; o < CLSN; o++) acc[o] = fmaf(hv, wrow[o], acc[o]);
        }
    }

    float* op = out + (size_t)q * CLSN;
    #pragma unroll
    for (int o = 0; o < CLSN; o++) op[o] = acc[o];
}

// ---------------- launch ---------------------------------------------------
extern "C" void kernel_launch(void* const* d_in, const int* in_sizes, int n_in,
                              void* d_out, int out_size)
{
    const float* coords_q = (const float*)d_in[0];
    const float* coords_s = (const float*)d_in[1];
    const float* x7       = (const float*)d_in[2];
    const float* feat_s7  = (const float*)d_in[3];
    const float* feat_s   = (const float*)d_in[4];
    const float* w_attn   = (const float*)d_in[5];
    const float* W1       = (const float*)d_in[6];
    const float* gamma    = (const float*)d_in[7];
    const float* beta     = (const float*)d_in[8];
    const float* W2       = (const float*)d_in[9];
    const float* W_cls    = (const float*)d_in[10];
    const float* b_cls    = (const float*)d_in[11];
    float* out = (float*)d_out;

    int NQ = in_sizes[0] / 3;
    int NS = in_sizes[1] / 3;
    int nparts = (NS + 63) / 64;          // k_gpool blocks (<=128)

    float* g_FS1p; cudaGetSymbolAddress((void**)&g_FS1p, g_FS1);
    float* g_XWp;  cudaGetSymbolAddress((void**)&g_XWp,  g_XW);

    k_prep<<<(NS + CC * CLSN + 255) / 256, 256>>>(coords_s, W2, W_cls, NS);
    k_logits<<<64, 256>>>(feat_s7, w_attn, NS);
    k_softmax<<<1, 1024>>>(NS);
    k_gpool<<<nparts, 256>>>(feat_s7, NS);
    k_gate<<<1, 128>>>(nparts);
    // FS1 = (feat_s @ W1_bot) * gamma (cols)
    k_sgemm112<<<(NS + 63) / 64, 256>>>(feat_s, W1 + CC * CC, g_FS1p, NS, 0, gamma);
    // XW  = (x7 @ diag(gate) W1_top) * gamma (cols)
    k_sgemm112<<<(NQ + 63) / 64, 256>>>(x7, W1, g_XWp, NQ, 1, gamma);
    k_final<<<(NQ + 31) / 32, 256>>>(coords_q, beta, b_cls, out, NQ, NS);
}